// round 4
// baseline (speedup 1.0000x reference)
#include <cuda_runtime.h>
#include <math.h>

#define PP 20000
#define TT 30
#define SS 1000
#define DD 128     // elem embedding dim
#define HH 128     // LSTM hidden
#define GG 512     // 4*H gate width
#define DPP 128    // proj out dim
#define EE 64      // leaf embedding dim

// ---------------- device scratch (static: no allocations allowed) ----------
__device__ float g_Hst[2][2][PP * HH];        // [dir][buf parity] hidden, PERMUTED rows
__device__ float g_Cst[2][PP * HH];           // [dir] cell, PERMUTED rows
__device__ float g_Br[2][256 * GG];           // tf32 [W;U], COLUMNS PERMUTED m=4j+q
__device__ float g_full[(size_t)PP * DPP];    // PERMUTED
__device__ float g_scores[PP];                // PERMUTED
__device__ int   g_mxe[SS];
__device__ float g_den[SS];
__device__ int   g_is64[2];
__device__ int   g_hist[TT + 2];
__device__ int   g_off[TT + 2];
__device__ int   g_perm[PP];                  // permuted row -> original path
__device__ int   g_cnt[TT];                   // #paths with len > s

// ---------------- helpers --------------------------------------------------
__device__ __forceinline__ int encf(float f) {
    int i = __float_as_int(f);
    return i >= 0 ? i : (i ^ 0x7fffffff);
}
__device__ __forceinline__ float decf(int i) {
    return __int_as_float(i >= 0 ? i : (i ^ 0x7fffffff));
}
__device__ __forceinline__ float totf(float x) {
    unsigned u;
    asm("cvt.rna.tf32.f32 %0, %1;" : "=r"(u) : "f"(x));
    return __uint_as_float(u);
}
__device__ __forceinline__ void mma_tf32(float* c, const unsigned* a, const unsigned* b) {
    asm volatile(
        "mma.sync.aligned.m16n8k8.row.col.f32.tf32.tf32.f32 "
        "{%0,%1,%2,%3}, {%4,%5,%6,%7}, {%8,%9}, {%0,%1,%2,%3};"
        : "+f"(c[0]), "+f"(c[1]), "+f"(c[2]), "+f"(c[3])
        : "r"(a[0]), "r"(a[1]), "r"(a[2]), "r"(a[3]), "r"(b[0]), "r"(b[1]));
}
__device__ __forceinline__ float sigf(float x) { return 1.f / (1.f + expf(-x)); }

// ---------------- init + dtype detection -----------------------------------
__global__ void init_kernel(const void* pe, const void* li, float* out) {
    long long i = (long long)blockIdx.x * blockDim.x + threadIdx.x;
    const long long NH = 4LL * PP * HH;             // all 4 h buffers
    if (i < NH) (&g_Hst[0][0][0])[i] = 0.f;
    long long j = i - NH;
    if (j >= 0 && j < 2LL * PP * HH) (&g_Cst[0][0])[j] = 0.f;
    j -= 2LL * PP * HH;
    if (j >= 0 && j < PP) g_scores[j] = 0.f;
    j -= PP;
    if (j >= 0 && j < SS) {
        g_den[j] = 0.f;
        g_mxe[j] = (int)0x80000000;
    }
    j -= SS;
    if (j >= 0 && j < (long long)SS * DPP) out[j] = 0.f;
    j -= (long long)SS * DPP;
    if (j >= 0 && j < TT + 2) g_hist[j] = 0;

    if (i == 0) {
        int a = 1, b = 1;
        const int* p32 = (const int*)pe;
        const int* l32 = (const int*)li;
        for (int k = 0; k < 64; k++) {
            if (p32[2 * k + 1] != 0) a = 0;
            if (l32[2 * k + 1] != 0) b = 0;
        }
        g_is64[0] = a;
        g_is64[1] = b;
    }
}

// ---------------- counting sort by length (descending) ----------------------
__global__ void hist_k(const int* __restrict__ lens) {
    int p = blockIdx.x * 256 + threadIdx.x;
    if (p < PP) {
        int L = lens[p];
        if (L < 0) L = 0;
        if (L > TT) L = TT;
        atomicAdd(&g_hist[L], 1);
    }
}
__global__ void scan_k() {
    if (threadIdx.x == 0 && blockIdx.x == 0) {
        int run = 0;
        for (int L = TT; L >= 0; --L) {
            g_off[L] = run;
            run += g_hist[L];
        }
        for (int s = 0; s < TT; s++) {
            int c = 0;
            for (int L = s + 1; L <= TT; L++) c += g_hist[L];
            g_cnt[s] = c;
        }
    }
}
__global__ void scatter_k(const int* __restrict__ lens) {
    int p = blockIdx.x * 256 + threadIdx.x;
    if (p < PP) {
        int L = lens[p];
        if (L < 0) L = 0;
        if (L > TT) L = TT;
        int slot = atomicAdd(&g_off[L], 1);
        g_perm[slot] = p;
    }
}

// ---------------- pre-round + column-permute weights to tf32 -----------------
// new col m = 4*j + q maps to original col q*128 + j.
__global__ void bround_k(const float* __restrict__ Wf, const float* __restrict__ Uf,
                         const float* __restrict__ Wb, const float* __restrict__ Ub)
{
    int i = blockIdx.x * 256 + threadIdx.x;
    if (i >= 2 * 256 * GG) return;
    int dir = i / (256 * GG);
    int r = i - dir * (256 * GG);
    int k = r / GG, m = r - k * GG;
    int oc = (m & 3) * 128 + (m >> 2);
    const float* W = dir ? Wb : Wf;
    const float* U = dir ? Ub : Uf;
    float v = (k < 128) ? W[(size_t)k * GG + oc] : U[(size_t)(k - 128) * GG + oc];
    g_Br[dir][r] = totf(v);
}

// ---------------- fused LSTM step: GEMM + gates + state update --------------
// grid: (157, 4, 2), 256 thr = 8 warps (4 M x 2 N), C tile 128x128 of permuted z.
// Column tile covers hidden j in [n0/4, n0/4+32), all 4 gates -> full state
// update done in-epilogue. h double-buffered by t parity; c owned per j-block.
__global__ __launch_bounds__(256, 2) void lstm_step(
    const float* __restrict__ emb, const void* __restrict__ pe,
    const float* __restrict__ bf, const float* __restrict__ bb, int t)
{
    const int dir = blockIdx.z;
    const int s   = dir ? (TT - 1 - t) : t;
    const int cnt = g_cnt[s];
    const int p0  = blockIdx.x * 128;
    if (p0 >= cnt) return;
    const int n0  = blockIdx.y * 128;
    const int tid = threadIdx.x;

    const float* __restrict__ Hold = g_Hst[dir][t & 1];
    float* __restrict__ Hnew = g_Hst[dir][(t + 1) & 1];
    float* __restrict__ Cd   = g_Cst[dir];
    const float* __restrict__ Bw = g_Br[dir];
    const float* bias = dir ? bb : bf;

    __shared__ float As[128][36];
    __shared__ float Bs[32][136];
    __shared__ int   sE[128];
    __shared__ float sBias[128];

    if (tid < 128) {
        int p = p0 + tid;
        if (p >= PP) p = PP - 1;
        int orig = g_perm[p];
        long long e;
        if (g_is64[0]) e = ((const long long*)pe)[(long long)orig * TT + s];
        else           e = ((const int*)pe)[orig * TT + s];
        sE[tid] = (int)e;
    } else {
        int u = tid - 128;               // 0..127
        int q = u >> 5, jl = u & 31;
        sBias[q * 32 + jl] = bias[q * 128 + (n0 >> 2) + jl];
    }
    __syncthreads();

    const int warp = tid >> 5, lane = tid & 31;
    const int grp = lane >> 2, tig = lane & 3;
    const int wm = warp >> 1, wn = warp & 1;

    float acc[2][8][4];
#pragma unroll
    for (int mt = 0; mt < 2; mt++)
#pragma unroll
        for (int nt = 0; nt < 8; nt++)
#pragma unroll
            for (int q = 0; q < 4; q++) acc[mt][nt][q] = 0.f;

    for (int ck = 0; ck < 8; ck++) {
        const int k0 = ck * 32;
#pragma unroll
        for (int it = 0; it < 4; it++) {
            int idx = tid + it * 256;
            int r = idx >> 3, kk = (idx & 7) * 4;
            int gk = k0 + kk;
            float4 v;
            if (gk < 128) {
                v = *(const float4*)&emb[(size_t)sE[r] * DD + gk];
            } else {
                int p = p0 + r;
                if (p >= PP) p = PP - 1;
                v = *(const float4*)&Hold[(size_t)p * HH + (gk - 128)];
            }
            float4 w = make_float4(totf(v.x), totf(v.y), totf(v.z), totf(v.w));
            *(float4*)&As[r][kk] = w;
        }
#pragma unroll
        for (int it = 0; it < 4; it++) {
            int idx = tid + it * 256;
            int kk = idx >> 5, c = (idx & 31) * 4;
            float4 v = *(const float4*)&Bw[(size_t)(k0 + kk) * GG + n0 + c];
            *(float4*)&Bs[kk][c] = v;
        }
        __syncthreads();

#pragma unroll
        for (int k8 = 0; k8 < 4; k8++) {
            const int kb = k8 * 8;
            unsigned a[2][4], b[8][2];
#pragma unroll
            for (int mt = 0; mt < 2; mt++) {
                int rb = wm * 32 + mt * 16;
                a[mt][0] = __float_as_uint(As[rb + grp][kb + tig]);
                a[mt][1] = __float_as_uint(As[rb + grp + 8][kb + tig]);
                a[mt][2] = __float_as_uint(As[rb + grp][kb + tig + 4]);
                a[mt][3] = __float_as_uint(As[rb + grp + 8][kb + tig + 4]);
            }
#pragma unroll
            for (int nt = 0; nt < 8; nt++) {
                int cb = wn * 64 + nt * 8 + grp;
                b[nt][0] = __float_as_uint(Bs[kb + tig][cb]);
                b[nt][1] = __float_as_uint(Bs[kb + tig + 4][cb]);
            }
#pragma unroll
            for (int mt = 0; mt < 2; mt++)
#pragma unroll
                for (int nt = 0; nt < 8; nt++)
                    mma_tf32(acc[mt][nt], a[mt], b[nt]);
        }
        __syncthreads();
    }

    // Fused gate epilogue. For each (mt, nt): this thread's cols are
    // mcol, mcol+1 with mcol = n0 + wn*64 + nt*8 + tig*2; gate quadruple of
    // hidden j = mcol>>2 is split across the (tig even, tig odd) lane pair.
#pragma unroll
    for (int mt = 0; mt < 2; mt++) {
        int prow = p0 + wm * 32 + mt * 16 + grp;
#pragma unroll
        for (int nt = 0; nt < 8; nt++) {
            int mcol = n0 + wn * 64 + nt * 8 + tig * 2;
            int j  = mcol >> 2;
            int jl = j - (n0 >> 2);
            float c0 = acc[mt][nt][0], c1 = acc[mt][nt][1];
            float c2 = acc[mt][nt][2], c3 = acc[mt][nt][3];
            // even lane sends row prow+8 pair (c2,c3); odd lane sends row prow pair (c0,c1)
            float s0 = (tig & 1) ? c0 : c2;
            float s1 = (tig & 1) ? c1 : c3;
            float r0 = __shfl_xor_sync(0xffffffff, s0, 1);
            float r1 = __shfl_xor_sync(0xffffffff, s1, 1);
            int p; float zi, zf, zg, zo;
            if ((tig & 1) == 0) { p = prow;     zi = c0; zf = c1; zg = r0; zo = r1; }
            else               { p = prow + 8; zi = r0; zf = r1; zg = c2; zo = c3; }
            if (p < cnt) {
                zi += sBias[jl];      zf += sBias[32 + jl];
                zg += sBias[64 + jl]; zo += sBias[96 + jl];
                float ig = sigf(zi), fg = sigf(zf);
                float gg = tanhf(zg), og = sigf(zo);
                size_t off = (size_t)p * HH + j;
                float c  = Cd[off];
                float cn = fg * c + ig * gg;
                Cd[off]   = cn;
                Hnew[off] = og * tanhf(cn);
            }
        }
    }
}

// ---------------- proj GEMM (tf32 mma): full = [leaf|h_f|h_b] @ proj --------
// grid (157), block 256. Per-row fwd h buffer parity = len&1; bwd in buf 0.
__global__ __launch_bounds__(256, 2) void proj_mma(
    const float* __restrict__ leafE, const void* __restrict__ li,
    const float* __restrict__ proj, const float* __restrict__ att,
    const int* __restrict__ lens)
{
    const int p0 = blockIdx.x * 128;
    const int tid = threadIdx.x;
    __shared__ float As[128][36];
    __shared__ float Bs[32][136];
    __shared__ int   sL[128][2];
    __shared__ int   sBuf[128];
    __shared__ float sAtt[128];

    {
        int r = tid >> 1, which = tid & 1;
        int p = p0 + r;
        if (p >= PP) p = PP - 1;
        int orig = g_perm[p];
        long long v;
        if (g_is64[1]) v = ((const long long*)li)[(long long)orig * 2 + which];
        else           v = ((const int*)li)[orig * 2 + which];
        sL[r][which] = (int)v;
    }
    if (tid < 128) {
        int p = p0 + tid;
        if (p >= PP) p = PP - 1;
        int L = lens[g_perm[p]];
        if (L < 0) L = 0;
        sBuf[tid] = L & 1;
        sAtt[tid] = att[tid];
    }
    __syncthreads();

    const int warp = tid >> 5, lane = tid & 31;
    const int grp = lane >> 2, tig = lane & 3;
    const int wm = warp >> 1, wn = warp & 1;

    float acc[2][8][4];
#pragma unroll
    for (int mt = 0; mt < 2; mt++)
#pragma unroll
        for (int nt = 0; nt < 8; nt++)
#pragma unroll
            for (int q = 0; q < 4; q++) acc[mt][nt][q] = 0.f;

    for (int ck = 0; ck < 12; ck++) {      // K = 384
        const int k0 = ck * 32;
#pragma unroll
        for (int it = 0; it < 4; it++) {
            int idx = tid + it * 256;
            int r = idx >> 3, kk = (idx & 7) * 4;
            int gk = k0 + kk;
            int p = p0 + r;
            if (p >= PP) p = PP - 1;
            float4 v;
            if (gk < 64)       v = *(const float4*)&leafE[(size_t)sL[r][0] * EE + gk];
            else if (gk < 128) v = *(const float4*)&leafE[(size_t)sL[r][1] * EE + (gk - 64)];
            else if (gk < 256) {
                const float* hf = g_Hst[0][sBuf[r]];
                v = *(const float4*)&hf[(size_t)p * HH + (gk - 128)];
            } else {
                v = *(const float4*)&g_Hst[1][0][(size_t)p * HH + (gk - 256)];
            }
            float4 w = make_float4(totf(v.x), totf(v.y), totf(v.z), totf(v.w));
            *(float4*)&As[r][kk] = w;
        }
#pragma unroll
        for (int it = 0; it < 4; it++) {
            int idx = tid + it * 256;
            int kk = idx >> 5, c = (idx & 31) * 4;
            float4 v = *(const float4*)&proj[(size_t)(k0 + kk) * DPP + c];
            float4 w = make_float4(totf(v.x), totf(v.y), totf(v.z), totf(v.w));
            *(float4*)&Bs[kk][c] = w;
        }
        __syncthreads();

#pragma unroll
        for (int k8 = 0; k8 < 4; k8++) {
            const int kb = k8 * 8;
            unsigned a[2][4], b[8][2];
#pragma unroll
            for (int mt = 0; mt < 2; mt++) {
                int rb = wm * 32 + mt * 16;
                a[mt][0] = __float_as_uint(As[rb + grp][kb + tig]);
                a[mt][1] = __float_as_uint(As[rb + grp + 8][kb + tig]);
                a[mt][2] = __float_as_uint(As[rb + grp][kb + tig + 4]);
                a[mt][3] = __float_as_uint(As[rb + grp + 8][kb + tig + 4]);
            }
#pragma unroll
            for (int nt = 0; nt < 8; nt++) {
                int cb = wn * 64 + nt * 8 + grp;
                b[nt][0] = __float_as_uint(Bs[kb + tig][cb]);
                b[nt][1] = __float_as_uint(Bs[kb + tig + 4][cb]);
            }
#pragma unroll
            for (int mt = 0; mt < 2; mt++)
#pragma unroll
                for (int nt = 0; nt < 8; nt++)
                    mma_tf32(acc[mt][nt], a[mt], b[nt]);
        }
        __syncthreads();
    }

    // epilogue: write g_full + fused score dot (full . att)
    float loc[4] = {0.f, 0.f, 0.f, 0.f};
#pragma unroll
    for (int mt = 0; mt < 2; mt++) {
        int pr = p0 + wm * 32 + mt * 16 + grp;
#pragma unroll
        for (int nt = 0; nt < 8; nt++) {
            int col = wn * 64 + nt * 8 + tig * 2;
            float a0 = sAtt[col], a1 = sAtt[col + 1];
            loc[mt * 2 + 0] += acc[mt][nt][0] * a0 + acc[mt][nt][1] * a1;
            loc[mt * 2 + 1] += acc[mt][nt][2] * a0 + acc[mt][nt][3] * a1;
            if (pr < PP)
                *(float2*)&g_full[(size_t)pr * DPP + col] =
                    make_float2(acc[mt][nt][0], acc[mt][nt][1]);
            if (pr + 8 < PP)
                *(float2*)&g_full[(size_t)(pr + 8) * DPP + col] =
                    make_float2(acc[mt][nt][2], acc[mt][nt][3]);
        }
    }
#pragma unroll
    for (int q = 0; q < 4; q++) {
        loc[q] += __shfl_xor_sync(0xffffffff, loc[q], 1);
        loc[q] += __shfl_xor_sync(0xffffffff, loc[q], 2);
    }
    if (tig == 0) {
#pragma unroll
        for (int mt = 0; mt < 2; mt++) {
            int pr = p0 + wm * 32 + mt * 16 + grp;
            if (pr < PP)     atomicAdd(&g_scores[pr], loc[mt * 2 + 0]);
            if (pr + 8 < PP) atomicAdd(&g_scores[pr + 8], loc[mt * 2 + 1]);
        }
    }
}

// ---------------- segment softmax + weighted accumulation ------------------
__global__ void seg_max_k(const int* __restrict__ seg) {
    int p = blockIdx.x * 256 + threadIdx.x;
    if (p < PP) atomicMax(&g_mxe[seg[g_perm[p]]], encf(g_scores[p]));
}
__global__ void seg_den_k(const int* __restrict__ seg) {
    int p = blockIdx.x * 256 + threadIdx.x;
    if (p < PP) {
        int s = seg[g_perm[p]];
        atomicAdd(&g_den[s], expf(g_scores[p] - decf(g_mxe[s])));
    }
}
__global__ void seg_out_k(const int* __restrict__ seg, float* __restrict__ out) {
    int idx = blockIdx.x * 256 + threadIdx.x;
    if (idx < PP * DPP) {
        int p = idx >> 7, j = idx & 127;
        int s = seg[g_perm[p]];
        float w = expf(g_scores[p] - decf(g_mxe[s])) / g_den[s];
        atomicAdd(&out[(size_t)s * DPP + j], w * g_full[idx]);
    }
}

// ---------------- launch ----------------------------------------------------
extern "C" void kernel_launch(void* const* d_in, const int* in_sizes, int n_in,
                              void* d_out, int out_size)
{
    (void)in_sizes; (void)n_in; (void)out_size;
    const float* leafE = (const float*)d_in[0];
    const float* emb   = (const float*)d_in[1];
    const float* Wf    = (const float*)d_in[2];
    const float* Uf    = (const float*)d_in[3];
    const float* bf    = (const float*)d_in[4];
    const float* Wb    = (const float*)d_in[5];
    const float* Ub    = (const float*)d_in[6];
    const float* bb    = (const float*)d_in[7];
    const float* proj  = (const float*)d_in[8];
    const float* att   = (const float*)d_in[9];
    const void*  pe    = d_in[10];
    const int*   lens  = (const int*)d_in[11];
    const void*  li    = d_in[12];
    const int*   seg   = (const int*)d_in[13];
    float* out = (float*)d_out;

    const long long initN = 6LL * PP * HH + PP + SS + (long long)SS * DPP + TT + 2;
    init_kernel<<<(unsigned)((initN + 255) / 256), 256>>>(pe, li, out);
    hist_k<<<(PP + 255) / 256, 256>>>(lens);
    scan_k<<<1, 32>>>();
    scatter_k<<<(PP + 255) / 256, 256>>>(lens);
    bround_k<<<(2 * 256 * GG + 255) / 256, 256>>>(Wf, Uf, Wb, Ub);

    dim3 ggrid((PP + 127) / 128, 4, 2);
    for (int t = 0; t < TT; t++) {
        lstm_step<<<ggrid, 256>>>(emb, pe, bf, bb, t);
    }
    proj_mma<<<(PP + 127) / 128, 256>>>(leafE, li, proj, att, lens);
    seg_max_k<<<(PP + 255) / 256, 256>>>(seg);
    seg_den_k<<<(PP + 255) / 256, 256>>>(seg);
    seg_out_k<<<(PP * DPP + 255) / 256, 256>>>(seg, out);
}